// round 1
// baseline (speedup 1.0000x reference)
#include <cuda_runtime.h>
#include <math.h>

#define BB 4
#define NN 384
#define DD 64
#define TJ 32
#define NTHREADS 256

// SMEM layout (in floats):
//  sW1:    0      .. 16384   (W_eu1 256x64)
//  sW2:    16384  .. 20480   (W_eu2 64x64)
//  sWg:    20480  .. 28672   (W_eg 128x64)
//  sWm:    28672  .. 40960   (W_msg 192x64)
//  sb1/sb2/sbg/sbm: 40960/41024/41088/41152 (64 each)
//  shi:    41216  (64)   h[b,i,:]
//  sHS:    41280  (32*65 = 2080)  h[b,j] tile, stride 65
//  sE:     43360  (2080)          e tile / later e_new, stride 65
//  sX:     45440  (32*257 = 8224) edge_in stride 257; reused: t1@0, de@2080, msg@4160 (stride 65)
//  sPart:  53664  (256)           agg partials
//  total:  53920 floats = 215680 bytes
#define SMEM_FLOATS 53920
#define SMEM_BYTES  (SMEM_FLOATS * 4)

__device__ float d_agg[BB * NN * DD];

__device__ __forceinline__ float fast_sigmoid(float x) {
    return 1.0f / (1.0f + __expf(-x));
}

// Tile GEMM segment: rows {r0, r0+16} x cols {cg, cg+16, cg+32, cg+48}
// Xs indexed with given stride (stride 0 => broadcast row, used for h_i segment).
// Wseg is klen x 64 row-major.
__device__ __forceinline__ void gemm_seg(float acc[2][4],
                                         const float* __restrict__ Xs, int stride,
                                         const float* __restrict__ Wseg, int klen,
                                         int r0, int cg)
{
#pragma unroll 4
    for (int k = 0; k < klen; k++) {
        float a0 = Xs[r0 * stride + k];
        float a1 = Xs[(r0 + 16) * stride + k];
        const float* wr = Wseg + k * 64;
        float w0 = wr[cg];
        float w1 = wr[cg + 16];
        float w2 = wr[cg + 32];
        float w3 = wr[cg + 48];
        acc[0][0] = fmaf(a0, w0, acc[0][0]);
        acc[0][1] = fmaf(a0, w1, acc[0][1]);
        acc[0][2] = fmaf(a0, w2, acc[0][2]);
        acc[0][3] = fmaf(a0, w3, acc[0][3]);
        acc[1][0] = fmaf(a1, w0, acc[1][0]);
        acc[1][1] = fmaf(a1, w1, acc[1][1]);
        acc[1][2] = fmaf(a1, w2, acc[1][2]);
        acc[1][3] = fmaf(a1, w3, acc[1][3]);
    }
}

__global__ void __launch_bounds__(NTHREADS, 1) edge_kernel(
    const float* __restrict__ h, const float* __restrict__ e,
    const float* __restrict__ W1, const float* __restrict__ b1,
    const float* __restrict__ W2, const float* __restrict__ b2,
    const float* __restrict__ Wg, const float* __restrict__ bg,
    const float* __restrict__ Wm, const float* __restrict__ bm,
    float* __restrict__ e_out)
{
    extern __shared__ float sm[];
    float* sW1 = sm;
    float* sW2 = sm + 16384;
    float* sWg = sm + 20480;
    float* sWm = sm + 28672;
    float* sb1 = sm + 40960;
    float* sb2 = sm + 41024;
    float* sbg = sm + 41088;
    float* sbm = sm + 41152;
    float* shi = sm + 41216;
    float* sHS = sm + 41280;          // stride 65
    float* sE  = sm + 43360;          // stride 65
    float* sX  = sm + 45440;          // edge_in stride 257
    float* sT1 = sX;                  // stride 65 (after GEMM1)
    float* sDE = sX + 2080;           // stride 65
    float* sMSG = sX + 4160;          // stride 65
    float* sPart = sm + 53664;        // 256

    const int tid = threadIdx.x;
    const int blk = blockIdx.x;
    const int b = blk / NN;
    const int i = blk - b * NN;

    // ---- Stage weights/biases/h_i into SMEM ----
    for (int idx = tid; idx < 16384 / 4; idx += NTHREADS)
        ((float4*)sW1)[idx] = ((const float4*)W1)[idx];
    for (int idx = tid; idx < 4096 / 4; idx += NTHREADS)
        ((float4*)sW2)[idx] = ((const float4*)W2)[idx];
    for (int idx = tid; idx < 8192 / 4; idx += NTHREADS)
        ((float4*)sWg)[idx] = ((const float4*)Wg)[idx];
    for (int idx = tid; idx < 12288 / 4; idx += NTHREADS)
        ((float4*)sWm)[idx] = ((const float4*)Wm)[idx];
    if (tid < 64) {
        sb1[tid] = b1[tid];
        sb2[tid] = b2[tid];
        sbg[tid] = bg[tid];
        sbm[tid] = bm[tid];
        shi[tid] = h[(b * NN + i) * DD + tid];
    }
    __syncthreads();

    const int r0 = tid & 15;
    const int cg = tid >> 4;
    const int ac = tid & 63;   // agg dim owned by this thread
    const int rq = tid >> 6;   // row-quarter for agg partial
    float aggp = 0.0f;

    for (int j0 = 0; j0 < NN; j0 += TJ) {
        // ---- Load h_j tile and e tile ----
        for (int idx = tid; idx < TJ * DD; idx += NTHREADS) {
            int r = idx >> 6, c = idx & 63;
            sHS[r * 65 + c] = h[(b * NN + (j0 + r)) * DD + c];
            sE[r * 65 + c]  = e[(((size_t)(b * NN + i)) * NN + (j0 + r)) * DD + c];
        }
        __syncthreads();

        // ---- Build edge_in = [hs+ht, |hs-ht|, hs*ht, e] ----
        for (int idx = tid; idx < TJ * DD; idx += NTHREADS) {
            int r = idx >> 6, c = idx & 63;
            float hs = sHS[r * 65 + c];
            float ht = shi[c];
            float* xr = sX + r * 257;
            xr[c]        = hs + ht;
            xr[64 + c]   = fabsf(hs - ht);
            xr[128 + c]  = hs * ht;
            xr[192 + c]  = sE[r * 65 + c];
        }
        __syncthreads();

        // ---- GEMM1: t1 = silu(edge_in @ W1 + b1) ----
        float acc[2][4] = {{0.f,0.f,0.f,0.f},{0.f,0.f,0.f,0.f}};
        gemm_seg(acc, sX, 257, sW1, 256, r0, cg);
        __syncthreads();  // edge_in reads complete before overwrite
#pragma unroll
        for (int rr = 0; rr < 2; rr++)
#pragma unroll
            for (int m = 0; m < 4; m++) {
                int c = cg + 16 * m;
                float v = acc[rr][m] + sb1[c];
                v = v * fast_sigmoid(v);
                sT1[(r0 + 16 * rr) * 65 + c] = v;
            }
        __syncthreads();

        // ---- GEMM2: de = t1 @ W2 + b2 ----
#pragma unroll
        for (int rr = 0; rr < 2; rr++)
#pragma unroll
            for (int m = 0; m < 4; m++) acc[rr][m] = 0.f;
        gemm_seg(acc, sT1, 65, sW2, 64, r0, cg);
#pragma unroll
        for (int rr = 0; rr < 2; rr++)
#pragma unroll
            for (int m = 0; m < 4; m++) {
                int c = cg + 16 * m;
                sDE[(r0 + 16 * rr) * 65 + c] = acc[rr][m] + sb2[c];
            }
        __syncthreads();

        // ---- GEMM3: eg = sigmoid([e, de] @ Wg + bg); e_new = eg*e + (1-eg)*de ----
#pragma unroll
        for (int rr = 0; rr < 2; rr++)
#pragma unroll
            for (int m = 0; m < 4; m++) acc[rr][m] = 0.f;
        gemm_seg(acc, sE, 65, sWg, 64, r0, cg);
        gemm_seg(acc, sDE, 65, sWg + 64 * 64, 64, r0, cg);
        float en[2][4];
#pragma unroll
        for (int rr = 0; rr < 2; rr++)
#pragma unroll
            for (int m = 0; m < 4; m++) {
                int c = cg + 16 * m;
                int r = r0 + 16 * rr;
                float g = fast_sigmoid(acc[rr][m] + sbg[c]);
                float ev = sE[r * 65 + c];
                float dv = sDE[r * 65 + c];
                en[rr][m] = g * ev + (1.0f - g) * dv;
            }
        __syncthreads();  // all sE reads complete
#pragma unroll
        for (int rr = 0; rr < 2; rr++)
#pragma unroll
            for (int m = 0; m < 4; m++)
                sE[(r0 + 16 * rr) * 65 + (cg + 16 * m)] = en[rr][m];
        __syncthreads();

        // ---- Write e_new to global (coalesced) ----
        for (int idx = tid; idx < TJ * DD; idx += NTHREADS) {
            int r = idx >> 6, c = idx & 63;
            e_out[(((size_t)(b * NN + i)) * NN + (j0 + r)) * DD + c] = sE[r * 65 + c];
        }

        // ---- GEMM4: msg = silu([hs, ht, e_new] @ Wm + bm) ----
#pragma unroll
        for (int rr = 0; rr < 2; rr++)
#pragma unroll
            for (int m = 0; m < 4; m++) acc[rr][m] = 0.f;
        gemm_seg(acc, sHS, 65, sWm, 64, r0, cg);
        gemm_seg(acc, shi, 0, sWm + 64 * 64, 64, r0, cg);
        gemm_seg(acc, sE, 65, sWm + 128 * 64, 64, r0, cg);
#pragma unroll
        for (int rr = 0; rr < 2; rr++)
#pragma unroll
            for (int m = 0; m < 4; m++) {
                int c = cg + 16 * m;
                float v = acc[rr][m] + sbm[c];
                v = v * fast_sigmoid(v);
                sMSG[(r0 + 16 * rr) * 65 + c] = v;
            }
        __syncthreads();

        // ---- Accumulate agg partials (skip diagonal j==i) ----
#pragma unroll
        for (int rr = 0; rr < 8; rr++) {
            int r = rq * 8 + rr;
            int j = j0 + r;
            if (j != i) aggp += sMSG[r * 65 + ac];
        }
        __syncthreads();  // sMSG reads complete before next tile reuses sX
    }

    // ---- Reduce agg partials and write ----
    sPart[tid] = aggp;
    __syncthreads();
    if (tid < 64) {
        float s = sPart[tid] + sPart[64 + tid] + sPart[128 + tid] + sPart[192 + tid];
        d_agg[(b * NN + i) * DD + tid] = s * (1.0f / (NN - 1));
    }
}

__global__ void __launch_bounds__(64) node_kernel(
    const float* __restrict__ h,
    const float* __restrict__ Wu, const float* __restrict__ bu,
    const float* __restrict__ Wg, const float* __restrict__ bg,
    float* __restrict__ h_out)
{
    __shared__ float xs[128];
    __shared__ float dhs[64];
    const int node = blockIdx.x;
    const int c = threadIdx.x;

    xs[c] = h[node * 64 + c];
    xs[64 + c] = d_agg[node * 64 + c];
    __syncthreads();

    float acc = bu[c];
#pragma unroll 8
    for (int k = 0; k < 128; k++)
        acc = fmaf(xs[k], Wu[k * 64 + c], acc);
    float dh = acc * fast_sigmoid(acc);
    dhs[c] = dh;
    __syncthreads();

    float a2 = bg[c];
#pragma unroll 8
    for (int k = 0; k < 64; k++)
        a2 = fmaf(xs[k], Wg[k * 64 + c], a2);
#pragma unroll 8
    for (int k = 0; k < 64; k++)
        a2 = fmaf(dhs[k], Wg[(64 + k) * 64 + c], a2);
    float g = fast_sigmoid(a2);
    h_out[node * 64 + c] = g * xs[c] + (1.0f - g) * dh;
}

extern "C" void kernel_launch(void* const* d_in, const int* in_sizes, int n_in,
                              void* d_out, int out_size)
{
    const float* h   = (const float*)d_in[0];
    const float* e   = (const float*)d_in[1];
    const float* W1  = (const float*)d_in[2];
    const float* b1  = (const float*)d_in[3];
    const float* W2  = (const float*)d_in[4];
    const float* b2  = (const float*)d_in[5];
    const float* Weg = (const float*)d_in[6];
    const float* beg = (const float*)d_in[7];
    const float* Wm  = (const float*)d_in[8];
    const float* bm  = (const float*)d_in[9];
    const float* Wu  = (const float*)d_in[10];
    const float* bu  = (const float*)d_in[11];
    const float* Wga = (const float*)d_in[12];
    const float* bga = (const float*)d_in[13];

    float* out = (float*)d_out;
    float* h_out = out;                       // (B,N,D)   = 98304 floats
    float* e_out = out + BB * NN * DD;        // (B,N,N,D) = 37748736 floats

    cudaFuncSetAttribute(edge_kernel, cudaFuncAttributeMaxDynamicSharedMemorySize, SMEM_BYTES);

    edge_kernel<<<BB * NN, NTHREADS, SMEM_BYTES>>>(
        h, e, W1, b1, W2, b2, Weg, beg, Wm, bm, e_out);
    node_kernel<<<BB * NN, 64>>>(h, Wu, bu, Wga, bga, h_out);
}

// round 2
// speedup vs baseline: 1.0030x; 1.0030x over previous
#include <cuda_runtime.h>
#include <math.h>

#define BB 4
#define NN 384
#define DD 64
#define TJ 32
#define NTHREADS 256

// SMEM layout (in floats):
//  sW1:    0      .. 16384   (W_eu1 256x64)
//  sW2:    16384  .. 20480   (W_eu2 64x64)
//  sWg:    20480  .. 28672   (W_eg 128x64)
//  sWm:    28672  .. 40960   (W_msg 192x64)
//  sb1/sb2/sbg/sbm: 40960/41024/41088/41152 (64 each)
//  shi:    41216  (64)   h[b,i,:]
//  sHS:    41280  (32*65 = 2080)  h[b,j] tile, stride 65
//  sE:     43360  (2080)          e tile / later e_new, stride 65
//  sX:     45440  (32*257 = 8224) edge_in stride 257; reused: t1@0, de@2080, msg@4160 (stride 65)
//  sPart:  53664  (256)           agg partials
//  total:  53920 floats = 215680 bytes
#define SMEM_FLOATS 53920
#define SMEM_BYTES  (SMEM_FLOATS * 4)

__device__ float d_agg[BB * NN * DD];

__device__ __forceinline__ float fast_sigmoid(float x) {
    return 1.0f / (1.0f + __expf(-x));
}

// Tile GEMM segment: rows {r0, r0+16} x cols {cg, cg+16, cg+32, cg+48}
// Xs indexed with given stride (stride 0 => broadcast row, used for h_i segment).
// Wseg is klen x 64 row-major.
__device__ __forceinline__ void gemm_seg(float acc[2][4],
                                         const float* __restrict__ Xs, int stride,
                                         const float* __restrict__ Wseg, int klen,
                                         int r0, int cg)
{
#pragma unroll 4
    for (int k = 0; k < klen; k++) {
        float a0 = Xs[r0 * stride + k];
        float a1 = Xs[(r0 + 16) * stride + k];
        const float* wr = Wseg + k * 64;
        float w0 = wr[cg];
        float w1 = wr[cg + 16];
        float w2 = wr[cg + 32];
        float w3 = wr[cg + 48];
        acc[0][0] = fmaf(a0, w0, acc[0][0]);
        acc[0][1] = fmaf(a0, w1, acc[0][1]);
        acc[0][2] = fmaf(a0, w2, acc[0][2]);
        acc[0][3] = fmaf(a0, w3, acc[0][3]);
        acc[1][0] = fmaf(a1, w0, acc[1][0]);
        acc[1][1] = fmaf(a1, w1, acc[1][1]);
        acc[1][2] = fmaf(a1, w2, acc[1][2]);
        acc[1][3] = fmaf(a1, w3, acc[1][3]);
    }
}

__global__ void __launch_bounds__(NTHREADS, 1) edge_kernel(
    const float* __restrict__ h, const float* __restrict__ e,
    const float* __restrict__ W1, const float* __restrict__ b1,
    const float* __restrict__ W2, const float* __restrict__ b2,
    const float* __restrict__ Wg, const float* __restrict__ bg,
    const float* __restrict__ Wm, const float* __restrict__ bm,
    float* __restrict__ e_out)
{
    extern __shared__ float sm[];
    float* sW1 = sm;
    float* sW2 = sm + 16384;
    float* sWg = sm + 20480;
    float* sWm = sm + 28672;
    float* sb1 = sm + 40960;
    float* sb2 = sm + 41024;
    float* sbg = sm + 41088;
    float* sbm = sm + 41152;
    float* shi = sm + 41216;
    float* sHS = sm + 41280;          // stride 65
    float* sE  = sm + 43360;          // stride 65
    float* sX  = sm + 45440;          // edge_in stride 257
    float* sT1 = sX;                  // stride 65 (after GEMM1)
    float* sDE = sX + 2080;           // stride 65
    float* sMSG = sX + 4160;          // stride 65
    float* sPart = sm + 53664;        // 256

    const int tid = threadIdx.x;
    const int blk = blockIdx.x;
    const int b = blk / NN;
    const int i = blk - b * NN;

    // ---- Stage weights/biases/h_i into SMEM ----
    for (int idx = tid; idx < 16384 / 4; idx += NTHREADS)
        ((float4*)sW1)[idx] = ((const float4*)W1)[idx];
    for (int idx = tid; idx < 4096 / 4; idx += NTHREADS)
        ((float4*)sW2)[idx] = ((const float4*)W2)[idx];
    for (int idx = tid; idx < 8192 / 4; idx += NTHREADS)
        ((float4*)sWg)[idx] = ((const float4*)Wg)[idx];
    for (int idx = tid; idx < 12288 / 4; idx += NTHREADS)
        ((float4*)sWm)[idx] = ((const float4*)Wm)[idx];
    if (tid < 64) {
        sb1[tid] = b1[tid];
        sb2[tid] = b2[tid];
        sbg[tid] = bg[tid];
        sbm[tid] = bm[tid];
        shi[tid] = h[(b * NN + i) * DD + tid];
    }
    __syncthreads();

    const int r0 = tid & 15;
    const int cg = tid >> 4;
    const int ac = tid & 63;   // agg dim owned by this thread
    const int rq = tid >> 6;   // row-quarter for agg partial
    float aggp = 0.0f;

    for (int j0 = 0; j0 < NN; j0 += TJ) {
        // ---- Load h_j tile and e tile ----
        for (int idx = tid; idx < TJ * DD; idx += NTHREADS) {
            int r = idx >> 6, c = idx & 63;
            sHS[r * 65 + c] = h[(b * NN + (j0 + r)) * DD + c];
            sE[r * 65 + c]  = e[(((size_t)(b * NN + i)) * NN + (j0 + r)) * DD + c];
        }
        __syncthreads();

        // ---- Build edge_in = [hs+ht, |hs-ht|, hs*ht, e] ----
        for (int idx = tid; idx < TJ * DD; idx += NTHREADS) {
            int r = idx >> 6, c = idx & 63;
            float hs = sHS[r * 65 + c];
            float ht = shi[c];
            float* xr = sX + r * 257;
            xr[c]        = hs + ht;
            xr[64 + c]   = fabsf(hs - ht);
            xr[128 + c]  = hs * ht;
            xr[192 + c]  = sE[r * 65 + c];
        }
        __syncthreads();

        // ---- GEMM1: t1 = silu(edge_in @ W1 + b1) ----
        float acc[2][4] = {{0.f,0.f,0.f,0.f},{0.f,0.f,0.f,0.f}};
        gemm_seg(acc, sX, 257, sW1, 256, r0, cg);
        __syncthreads();  // edge_in reads complete before overwrite
#pragma unroll
        for (int rr = 0; rr < 2; rr++)
#pragma unroll
            for (int m = 0; m < 4; m++) {
                int c = cg + 16 * m;
                float v = acc[rr][m] + sb1[c];
                v = v * fast_sigmoid(v);
                sT1[(r0 + 16 * rr) * 65 + c] = v;
            }
        __syncthreads();

        // ---- GEMM2: de = t1 @ W2 + b2 ----
#pragma unroll
        for (int rr = 0; rr < 2; rr++)
#pragma unroll
            for (int m = 0; m < 4; m++) acc[rr][m] = 0.f;
        gemm_seg(acc, sT1, 65, sW2, 64, r0, cg);
#pragma unroll
        for (int rr = 0; rr < 2; rr++)
#pragma unroll
            for (int m = 0; m < 4; m++) {
                int c = cg + 16 * m;
                sDE[(r0 + 16 * rr) * 65 + c] = acc[rr][m] + sb2[c];
            }
        __syncthreads();

        // ---- GEMM3: eg = sigmoid([e, de] @ Wg + bg); e_new = eg*e + (1-eg)*de ----
#pragma unroll
        for (int rr = 0; rr < 2; rr++)
#pragma unroll
            for (int m = 0; m < 4; m++) acc[rr][m] = 0.f;
        gemm_seg(acc, sE, 65, sWg, 64, r0, cg);
        gemm_seg(acc, sDE, 65, sWg + 64 * 64, 64, r0, cg);
        float en[2][4];
#pragma unroll
        for (int rr = 0; rr < 2; rr++)
#pragma unroll
            for (int m = 0; m < 4; m++) {
                int c = cg + 16 * m;
                int r = r0 + 16 * rr;
                float g = fast_sigmoid(acc[rr][m] + sbg[c]);
                float ev = sE[r * 65 + c];
                float dv = sDE[r * 65 + c];
                en[rr][m] = g * ev + (1.0f - g) * dv;
            }
        __syncthreads();  // all sE reads complete
#pragma unroll
        for (int rr = 0; rr < 2; rr++)
#pragma unroll
            for (int m = 0; m < 4; m++)
                sE[(r0 + 16 * rr) * 65 + (cg + 16 * m)] = en[rr][m];
        __syncthreads();

        // ---- Write e_new to global (coalesced) ----
        for (int idx = tid; idx < TJ * DD; idx += NTHREADS) {
            int r = idx >> 6, c = idx & 63;
            e_out[(((size_t)(b * NN + i)) * NN + (j0 + r)) * DD + c] = sE[r * 65 + c];
        }

        // ---- GEMM4: msg = silu([hs, ht, e_new] @ Wm + bm) ----
#pragma unroll
        for (int rr = 0; rr < 2; rr++)
#pragma unroll
            for (int m = 0; m < 4; m++) acc[rr][m] = 0.f;
        gemm_seg(acc, sHS, 65, sWm, 64, r0, cg);
        gemm_seg(acc, shi, 0, sWm + 64 * 64, 64, r0, cg);
        gemm_seg(acc, sE, 65, sWm + 128 * 64, 64, r0, cg);
#pragma unroll
        for (int rr = 0; rr < 2; rr++)
#pragma unroll
            for (int m = 0; m < 4; m++) {
                int c = cg + 16 * m;
                float v = acc[rr][m] + sbm[c];
                v = v * fast_sigmoid(v);
                sMSG[(r0 + 16 * rr) * 65 + c] = v;
            }
        __syncthreads();

        // ---- Accumulate agg partials (skip diagonal j==i) ----
#pragma unroll
        for (int rr = 0; rr < 8; rr++) {
            int r = rq * 8 + rr;
            int j = j0 + r;
            if (j != i) aggp += sMSG[r * 65 + ac];
        }
        __syncthreads();  // sMSG reads complete before next tile reuses sX
    }

    // ---- Reduce agg partials and write ----
    sPart[tid] = aggp;
    __syncthreads();
    if (tid < 64) {
        float s = sPart[tid] + sPart[64 + tid] + sPart[128 + tid] + sPart[192 + tid];
        d_agg[(b * NN + i) * DD + tid] = s * (1.0f / (NN - 1));
    }
}

__global__ void __launch_bounds__(64) node_kernel(
    const float* __restrict__ h,
    const float* __restrict__ Wu, const float* __restrict__ bu,
    const float* __restrict__ Wg, const float* __restrict__ bg,
    float* __restrict__ h_out)
{
    __shared__ float xs[128];
    __shared__ float dhs[64];
    const int node = blockIdx.x;
    const int c = threadIdx.x;

    xs[c] = h[node * 64 + c];
    xs[64 + c] = d_agg[node * 64 + c];
    __syncthreads();

    float acc = bu[c];
#pragma unroll 8
    for (int k = 0; k < 128; k++)
        acc = fmaf(xs[k], Wu[k * 64 + c], acc);
    float dh = acc * fast_sigmoid(acc);
    dhs[c] = dh;
    __syncthreads();

    float a2 = bg[c];
#pragma unroll 8
    for (int k = 0; k < 64; k++)
        a2 = fmaf(xs[k], Wg[k * 64 + c], a2);
#pragma unroll 8
    for (int k = 0; k < 64; k++)
        a2 = fmaf(dhs[k], Wg[(64 + k) * 64 + c], a2);
    float g = fast_sigmoid(a2);
    h_out[node * 64 + c] = g * xs[c] + (1.0f - g) * dh;
}

extern "C" void kernel_launch(void* const* d_in, const int* in_sizes, int n_in,
                              void* d_out, int out_size)
{
    const float* h   = (const float*)d_in[0];
    const float* e   = (const float*)d_in[1];
    const float* W1  = (const float*)d_in[2];
    const float* b1  = (const float*)d_in[3];
    const float* W2  = (const float*)d_in[4];
    const float* b2  = (const float*)d_in[5];
    const float* Weg = (const float*)d_in[6];
    const float* beg = (const float*)d_in[7];
    const float* Wm  = (const float*)d_in[8];
    const float* bm  = (const float*)d_in[9];
    const float* Wu  = (const float*)d_in[10];
    const float* bu  = (const float*)d_in[11];
    const float* Wga = (const float*)d_in[12];
    const float* bga = (const float*)d_in[13];

    float* out = (float*)d_out;
    float* h_out = out;                       // (B,N,D)   = 98304 floats
    float* e_out = out + BB * NN * DD;        // (B,N,N,D) = 37748736 floats

    cudaFuncSetAttribute(edge_kernel, cudaFuncAttributeMaxDynamicSharedMemorySize, SMEM_BYTES);

    edge_kernel<<<BB * NN, NTHREADS, SMEM_BYTES>>>(
        h, e, W1, b1, W2, b2, Weg, beg, Wm, bm, e_out);
    node_kernel<<<BB * NN, 64>>>(h, Wu, bu, Wga, bga, h_out);
}

// round 3
// speedup vs baseline: 3.1404x; 3.1309x over previous
#include <cuda_runtime.h>
#include <cuda_bf16.h>
#include <math.h>

#define BB 4
#define NN 384
#define DD 64
#define TJ 32
#define NTH 256

// 36 k16-steps total: GEMM1 (K=256) kk 0-15, GEMM2 (K=64) kk 16-19,
// GEMM3 (K=128: e kk 20-23, de kk 24-27), GEMM4 (K=128: hs kk 28-31, e_new kk 32-35)
#define KK_TOTAL 36
#define WFRAG_U32 (KK_TOTAL * 8 * 32 * 2)   // 18432 u32 per plane

__device__ unsigned g_Wfh[WFRAG_U32];
__device__ unsigned g_Wfl[WFRAG_U32];
__device__ float d_agg[BB * NN * DD];

// ---- SMEM layout in u32 units ----
#define OFF_WH   0
#define OFF_WL   18432
#define OFF_XH   36864      // 32 x 132 (pairs), edge_in hi plane
#define OFF_XL   41088
#define OFF_HSH  45312      // 32 x 36
#define OFF_HSL  46464
#define OFF_EH   47616
#define OFF_EL   48768
#define OFF_T1H  49920
#define OFF_T1L  51072
#define OFF_DEH  52224
#define OFF_DEL  53376
#define OFF_SHI  54528      // 64 floats (h_i)
#define OFF_B1   54592
#define OFF_B2   54656
#define OFF_BG   54720
#define OFF_BMP  54784
#define OFF_RED  54848      // 128 floats
#define SMEM_U32 54976
#define SMEM_BYTES (SMEM_U32 * 4)

#define XSTRIDE 132   // pairs per row (256 bf16 + 8 pad)
#define PSTRIDE 36    // pairs per row for 64-wide planes (64 + 8 pad)

__device__ __forceinline__ float fast_sigmoid(float x) {
    return 1.0f / (1.0f + __expf(-x));
}
__device__ __forceinline__ float silu(float x) { return x * fast_sigmoid(x); }

// split two fp32 into packed bf16 hi-pair and lo-pair
__device__ __forceinline__ void splitpk(float v0, float v1, unsigned &whi, unsigned &wlo) {
    __nv_bfloat16 h0 = __float2bfloat16(v0);
    __nv_bfloat16 h1 = __float2bfloat16(v1);
    float r0 = v0 - __bfloat162float(h0);
    float r1 = v1 - __bfloat162float(h1);
    __nv_bfloat16 l0 = __float2bfloat16(r0);
    __nv_bfloat16 l1 = __float2bfloat16(r1);
    whi = ((unsigned)__bfloat16_as_ushort(h1) << 16) | (unsigned)__bfloat16_as_ushort(h0);
    wlo = ((unsigned)__bfloat16_as_ushort(l1) << 16) | (unsigned)__bfloat16_as_ushort(l0);
}
__device__ __forceinline__ void up2(unsigned w, float &f0, float &f1) {
    f0 = __bfloat162float(__ushort_as_bfloat16((unsigned short)(w & 0xffffu)));
    f1 = __bfloat162float(__ushort_as_bfloat16((unsigned short)(w >> 16)));
}

__device__ __forceinline__ void mma4(float *d, const unsigned *a, uint2 b) {
    asm("mma.sync.aligned.m16n8k16.row.col.f32.bf16.bf16.f32 "
        "{%0,%1,%2,%3}, {%4,%5,%6,%7}, {%8,%9}, {%0,%1,%2,%3};"
        : "+f"(d[0]), "+f"(d[1]), "+f"(d[2]), "+f"(d[3])
        : "r"(a[0]), "r"(a[1]), "r"(a[2]), "r"(a[3]), "r"(b.x), "r"(b.y));
}

// One GEMM chunk: NKL k16 steps; A from planes (hi/lo), B from smem frag arrays.
template <int NKL>
__device__ __forceinline__ void do_gemm(float (&d)[2][4],
    const uint2 *Bh, const uint2 *Bl,
    const unsigned *pH, const unsigned *pL,
    int strideU, int kkStart, int wr, int wc, int g, int t)
{
    const int rowBase = (16 * wr + g) * strideU;
    const int row8 = 8 * strideU;
    const int lane = g * 4 + t;
#pragma unroll
    for (int kl = 0; kl < NKL; kl++) {
        const int kp = kl * 8 + t;
        unsigned ah[4], al[4];
        ah[0] = pH[rowBase + kp];
        ah[1] = pH[rowBase + row8 + kp];
        ah[2] = pH[rowBase + kp + 4];
        ah[3] = pH[rowBase + row8 + kp + 4];
        al[0] = pL[rowBase + kp];
        al[1] = pL[rowBase + row8 + kp];
        al[2] = pL[rowBase + kp + 4];
        al[3] = pL[rowBase + row8 + kp + 4];
        const int kk = kkStart + kl;
#pragma unroll
        for (int s = 0; s < 2; s++) {
            const int idx = ((kk * 8) + (wc * 2 + s)) * 32 + lane;
            uint2 bh = Bh[idx];
            uint2 bl = Bl[idx];
            mma4(d[s], ah, bh);
            mma4(d[s], ah, bl);
            mma4(d[s], al, bh);
        }
    }
}

// ---- Precompute weight fragments (B-fragment layout, hi/lo bf16 planes) ----
__global__ void prep_kernel(const float *__restrict__ W1, const float *__restrict__ W2,
                            const float *__restrict__ Wg, const float *__restrict__ Wm)
{
    const int kk = blockIdx.x;            // 0..35
    const int t = threadIdx.x;            // 256
    const int nt = t >> 5;                // 0..7
    const int lane = t & 31;
    const int g = lane >> 2;
    const int tt = lane & 3;
    const int n = nt * 8 + g;
    const int k0 = tt * 2;

    const float *W;
    int kb;
    if (kk < 16)      { W = W1; kb = kk * 16; }
    else if (kk < 20) { W = W2; kb = (kk - 16) * 16; }
    else if (kk < 28) { W = Wg; kb = (kk - 20) * 16; }
    else if (kk < 32) { W = Wm; kb = (kk - 28) * 16; }          // hs rows 0-63
    else              { W = Wm; kb = 128 + (kk - 32) * 16; }    // e_new rows 128-191

    float w0 = W[(kb + k0) * 64 + n];
    float w1 = W[(kb + k0 + 1) * 64 + n];
    float w2 = W[(kb + k0 + 8) * 64 + n];
    float w3 = W[(kb + k0 + 9) * 64 + n];

    unsigned h0, l0, h1, l1;
    splitpk(w0, w1, h0, l0);
    splitpk(w2, w3, h1, l1);
    const int idx = ((kk * 8 + nt) * 32 + lane) * 2;
    g_Wfh[idx] = h0; g_Wfh[idx + 1] = h1;
    g_Wfl[idx] = l0; g_Wfl[idx + 1] = l1;
}

__global__ void __launch_bounds__(NTH, 1) edge_kernel(
    const float *__restrict__ h, const float *__restrict__ e,
    const float *__restrict__ b1, const float *__restrict__ b2,
    const float *__restrict__ bg, const float *__restrict__ bm,
    const float *__restrict__ Wm,
    float *__restrict__ e_out)
{
    extern __shared__ unsigned smu[];
    unsigned *sWh = smu + OFF_WH;
    unsigned *sWl = smu + OFF_WL;
    unsigned *sXh = smu + OFF_XH;
    unsigned *sXl = smu + OFF_XL;
    unsigned *sHSh = smu + OFF_HSH;
    unsigned *sHSl = smu + OFF_HSL;
    unsigned *sEh = smu + OFF_EH;
    unsigned *sEl = smu + OFF_EL;
    unsigned *sT1h = smu + OFF_T1H;
    unsigned *sT1l = smu + OFF_T1L;
    unsigned *sDEh = smu + OFF_DEH;
    unsigned *sDEl = smu + OFF_DEL;
    float *shi = (float *)(smu + OFF_SHI);
    float *sb1 = (float *)(smu + OFF_B1);
    float *sb2 = (float *)(smu + OFF_B2);
    float *sbg = (float *)(smu + OFF_BG);
    float *sbmp = (float *)(smu + OFF_BMP);
    float *sRed = (float *)(smu + OFF_RED);

    const uint2 *Bh = (const uint2 *)sWh;
    const uint2 *Bl = (const uint2 *)sWl;

    const int tid = threadIdx.x;
    const int blk = blockIdx.x;
    const int b = blk / NN;
    const int i = blk - b * NN;

    const int warp = tid >> 5;
    const int lane = tid & 31;
    const int wr = warp >> 2;   // 0..1: row half
    const int wc = warp & 3;    // 0..3: 16-col slab
    const int g = lane >> 2;
    const int t = lane & 3;

    // ---- stage weight fragments into smem (coalesced) ----
    {
        const uint4 *srcH = (const uint4 *)g_Wfh;
        const uint4 *srcL = (const uint4 *)g_Wfl;
        uint4 *dstH = (uint4 *)sWh;
        uint4 *dstL = (uint4 *)sWl;
        for (int idx = tid; idx < WFRAG_U32 / 4; idx += NTH) {
            dstH[idx] = srcH[idx];
            dstL[idx] = srcL[idx];
        }
    }
    if (tid < 64) {
        shi[tid] = h[(b * NN + i) * DD + tid];
        sb1[tid] = b1[tid];
        sb2[tid] = b2[tid];
        sbg[tid] = bg[tid];
    }
    __syncthreads();
    // bm' = bm + ht @ Wm[64:128]  (rank-1 hoist of the ht block of GEMM4)
    if (tid < 64) {
        float acc = bm[tid];
#pragma unroll 8
        for (int k = 0; k < 64; k++)
            acc = fmaf(shi[k], Wm[(64 + k) * 64 + tid], acc);
        sbmp[tid] = acc;
    }

    float aggp[2][2] = {{0.f, 0.f}, {0.f, 0.f}};
    const size_t erow = ((size_t)(b * NN + i)) * NN;

    for (int j0 = 0; j0 < NN; j0 += TJ) {
        __syncthreads();   // prior-tile GEMM4 reads done before overwrite

        // ---- Stage A: load hs/e, build split planes + edge_in planes ----
#pragma unroll
        for (int p = 0; p < 4; p++) {
            const int idx = tid + p * NTH;      // 0..1023
            const int r = idx >> 5;
            const int cp = idx & 31;
            const int c = cp * 2;
            const float2 hs2 = *(const float2 *)&h[(b * NN + (j0 + r)) * DD + c];
            const float2 e2  = *(const float2 *)&e[(erow + (j0 + r)) * DD + c];
            const float ht0 = shi[c], ht1 = shi[c + 1];
            unsigned wh, wl;
            splitpk(hs2.x + ht0, hs2.y + ht1, wh, wl);
            sXh[r * XSTRIDE + cp] = wh;       sXl[r * XSTRIDE + cp] = wl;
            splitpk(fabsf(hs2.x - ht0), fabsf(hs2.y - ht1), wh, wl);
            sXh[r * XSTRIDE + 32 + cp] = wh;  sXl[r * XSTRIDE + 32 + cp] = wl;
            splitpk(hs2.x * ht0, hs2.y * ht1, wh, wl);
            sXh[r * XSTRIDE + 64 + cp] = wh;  sXl[r * XSTRIDE + 64 + cp] = wl;
            splitpk(e2.x, e2.y, wh, wl);
            sXh[r * XSTRIDE + 96 + cp] = wh;  sXl[r * XSTRIDE + 96 + cp] = wl;
            sEh[r * PSTRIDE + cp] = wh;       sEl[r * PSTRIDE + cp] = wl;
            splitpk(hs2.x, hs2.y, wh, wl);
            sHSh[r * PSTRIDE + cp] = wh;      sHSl[r * PSTRIDE + cp] = wl;
        }
        __syncthreads();

        const int rg = 16 * wr + g;           // tile-local output row
        const int cp0 = 8 * wc + t;           // pair col for s=0 (s adds 4)

        // ---- GEMM1: t1 = silu(edge_in @ W1 + b1) ----
        {
            float d[2][4] = {{0, 0, 0, 0}, {0, 0, 0, 0}};
            do_gemm<16>(d, Bh, Bl, sXh, sXl, XSTRIDE, 0, wr, wc, g, t);
#pragma unroll
            for (int s = 0; s < 2; s++) {
                const int cb = 16 * wc + 8 * s + 2 * t;
                const float bb0 = sb1[cb], bb1 = sb1[cb + 1];
                unsigned wh, wl;
                splitpk(silu(d[s][0] + bb0), silu(d[s][1] + bb1), wh, wl);
                sT1h[rg * PSTRIDE + cp0 + 4 * s] = wh;
                sT1l[rg * PSTRIDE + cp0 + 4 * s] = wl;
                splitpk(silu(d[s][2] + bb0), silu(d[s][3] + bb1), wh, wl);
                sT1h[(rg + 8) * PSTRIDE + cp0 + 4 * s] = wh;
                sT1l[(rg + 8) * PSTRIDE + cp0 + 4 * s] = wl;
            }
        }
        __syncthreads();

        // ---- GEMM2: de = t1 @ W2 + b2 ----
        {
            float d[2][4] = {{0, 0, 0, 0}, {0, 0, 0, 0}};
            do_gemm<4>(d, Bh, Bl, sT1h, sT1l, PSTRIDE, 16, wr, wc, g, t);
#pragma unroll
            for (int s = 0; s < 2; s++) {
                const int cb = 16 * wc + 8 * s + 2 * t;
                const float bb0 = sb2[cb], bb1 = sb2[cb + 1];
                unsigned wh, wl;
                splitpk(d[s][0] + bb0, d[s][1] + bb1, wh, wl);
                sDEh[rg * PSTRIDE + cp0 + 4 * s] = wh;
                sDEl[rg * PSTRIDE + cp0 + 4 * s] = wl;
                splitpk(d[s][2] + bb0, d[s][3] + bb1, wh, wl);
                sDEh[(rg + 8) * PSTRIDE + cp0 + 4 * s] = wh;
                sDEl[(rg + 8) * PSTRIDE + cp0 + 4 * s] = wl;
            }
        }
        __syncthreads();

        // ---- GEMM3: eg = sigmoid([e,de]@Wg+bg); e_new = eg*e + (1-eg)*de ----
        float en[2][2][2];
        {
            float d[2][4] = {{0, 0, 0, 0}, {0, 0, 0, 0}};
            do_gemm<4>(d, Bh, Bl, sEh, sEl, PSTRIDE, 20, wr, wc, g, t);
            do_gemm<4>(d, Bh, Bl, sDEh, sDEl, PSTRIDE, 24, wr, wc, g, t);
#pragma unroll
            for (int s = 0; s < 2; s++) {
                const int cb = 16 * wc + 8 * s + 2 * t;
                const int cp = cp0 + 4 * s;
                const float bg0 = sbg[cb], bg1 = sbg[cb + 1];
#pragma unroll
                for (int rh = 0; rh < 2; rh++) {
                    const int row = rg + 8 * rh;
                    float e0, e1, el0, el1, de0, de1, dl0, dl1;
                    up2(sEh[row * PSTRIDE + cp], e0, e1);
                    up2(sEl[row * PSTRIDE + cp], el0, el1);
                    up2(sDEh[row * PSTRIDE + cp], de0, de1);
                    up2(sDEl[row * PSTRIDE + cp], dl0, dl1);
                    e0 += el0; e1 += el1; de0 += dl0; de1 += dl1;
                    const float g0 = fast_sigmoid(d[s][2 * rh] + bg0);
                    const float g1 = fast_sigmoid(d[s][2 * rh + 1] + bg1);
                    en[s][rh][0] = g0 * e0 + (1.0f - g0) * de0;
                    en[s][rh][1] = g1 * e1 + (1.0f - g1) * de1;
                }
            }
        }
        __syncthreads();   // all reads of sE done before overwrite
#pragma unroll
        for (int s = 0; s < 2; s++) {
            const int cb = 16 * wc + 8 * s + 2 * t;
            const int cp = cp0 + 4 * s;
#pragma unroll
            for (int rh = 0; rh < 2; rh++) {
                const int row = rg + 8 * rh;
                unsigned wh, wl;
                splitpk(en[s][rh][0], en[s][rh][1], wh, wl);
                sEh[row * PSTRIDE + cp] = wh;
                sEl[row * PSTRIDE + cp] = wl;
                float2 v; v.x = en[s][rh][0]; v.y = en[s][rh][1];
                *(float2 *)&e_out[(erow + (j0 + row)) * DD + cb] = v;
            }
        }
        __syncthreads();

        // ---- GEMM4: msg = silu([hs, ht, e_new]@Wm + bm)  (ht folded into bm') ----
        {
            float d[2][4] = {{0, 0, 0, 0}, {0, 0, 0, 0}};
            do_gemm<4>(d, Bh, Bl, sHSh, sHSl, PSTRIDE, 28, wr, wc, g, t);
            do_gemm<4>(d, Bh, Bl, sEh, sEl, PSTRIDE, 32, wr, wc, g, t);
#pragma unroll
            for (int s = 0; s < 2; s++) {
                const int cb = 16 * wc + 8 * s + 2 * t;
                const float bb0 = sbmp[cb], bb1 = sbmp[cb + 1];
                const int j0g = j0 + rg;
                const float v00 = silu(d[s][0] + bb0);
                const float v01 = silu(d[s][1] + bb1);
                const float v10 = silu(d[s][2] + bb0);
                const float v11 = silu(d[s][3] + bb1);
                if (j0g != i)     { aggp[s][0] += v00; aggp[s][1] += v01; }
                if (j0g + 8 != i) { aggp[s][0] += v10; aggp[s][1] += v11; }
            }
        }
    }

    // ---- reduce agg: sum over g-lanes (same t share same cols) ----
#pragma unroll
    for (int s = 0; s < 2; s++)
#pragma unroll
        for (int o = 0; o < 2; o++) {
            float v = aggp[s][o];
            v += __shfl_xor_sync(0xffffffffu, v, 4);
            v += __shfl_xor_sync(0xffffffffu, v, 8);
            v += __shfl_xor_sync(0xffffffffu, v, 16);
            aggp[s][o] = v;
        }
    if (lane < 4) {
#pragma unroll
        for (int s = 0; s < 2; s++)
#pragma unroll
            for (int o = 0; o < 2; o++)
                sRed[wr * 64 + 16 * wc + 8 * s + 2 * lane + o] = aggp[s][o];
    }
    __syncthreads();
    if (tid < 64)
        d_agg[(b * NN + i) * DD + tid] = (sRed[tid] + sRed[64 + tid]) * (1.0f / (NN - 1));
}

__global__ void __launch_bounds__(64) node_kernel(
    const float *__restrict__ h,
    const float *__restrict__ Wu, const float *__restrict__ bu,
    const float *__restrict__ Wg, const float *__restrict__ bg,
    float *__restrict__ h_out)
{
    __shared__ float xs[128];
    __shared__ float dhs[64];
    const int node = blockIdx.x;
    const int c = threadIdx.x;

    xs[c] = h[node * 64 + c];
    xs[64 + c] = d_agg[node * 64 + c];
    __syncthreads();

    float acc = bu[c];
#pragma unroll 8
    for (int k = 0; k < 128; k++)
        acc = fmaf(xs[k], Wu[k * 64 + c], acc);
    float dh = acc * fast_sigmoid(acc);
    dhs[c] = dh;
    __syncthreads();

    float a2 = bg[c];
#pragma unroll 8
    for (int k = 0; k < 64; k++)
        a2 = fmaf(xs[k], Wg[k * 64 + c], a2);
#pragma unroll 8
    for (int k = 0; k < 64; k++)
        a2 = fmaf(dhs[k], Wg[(64 + k) * 64 + c], a2);
    float gg = fast_sigmoid(a2);
    h_out[node * 64 + c] = gg * xs[c] + (1.0f - gg) * dh;
}

extern "C" void kernel_launch(void* const* d_in, const int* in_sizes, int n_in,
                              void* d_out, int out_size)
{
    const float* h   = (const float*)d_in[0];
    const float* e   = (const float*)d_in[1];
    const float* W1  = (const float*)d_in[2];
    const float* b1  = (const float*)d_in[3];
    const float* W2  = (const float*)d_in[4];
    const float* b2  = (const float*)d_in[5];
    const float* Weg = (const float*)d_in[6];
    const float* beg = (const float*)d_in[7];
    const float* Wm  = (const float*)d_in[8];
    const float* bm  = (const float*)d_in[9];
    const float* Wu  = (const float*)d_in[10];
    const float* bu  = (const float*)d_in[11];
    const float* Wga = (const float*)d_in[12];
    const float* bga = (const float*)d_in[13];

    float* out = (float*)d_out;
    float* h_out = out;                       // (B,N,D)
    float* e_out = out + BB * NN * DD;        // (B,N,N,D)

    cudaFuncSetAttribute(edge_kernel, cudaFuncAttributeMaxDynamicSharedMemorySize, SMEM_BYTES);

    prep_kernel<<<KK_TOTAL, NTH>>>(W1, W2, Weg, Wm);
    edge_kernel<<<BB * NN, NTH, SMEM_BYTES>>>(h, e, b1, b2, beg, bm, Wm, e_out);
    node_kernel<<<BB * NN, 64>>>(h, Wu, bu, Wga, bga, h_out);
}

// round 4
// speedup vs baseline: 3.4055x; 1.0844x over previous
#include <cuda_runtime.h>
#include <cuda_bf16.h>
#include <math.h>

#define BB 4
#define NN 384
#define DD 64
#define TJ 32
#define NTH 256

// k16-steps: GEMM1 (K=256) kk 0-15, GEMM2 kk 16-19, GEMM3 (e kk20-23, de kk24-27),
// GEMM4 (hs kk28-31, e_new kk32-35). ht-block of W_msg hoisted into bias.
#define KK_TOTAL 36

__device__ uint4 g_Wf[KK_TOTAL * 8 * 32];   // B-frags: {bh.x,bh.y,bl.x,bl.y}
__device__ float d_agg[BB * NN * DD];

// ---- SMEM layout (u32 units). A-frag chunk = 32 lanes x uint4 = 128 u32, padded to 136.
#define CH 136
#define OFF_W    0          // 36864 u32 (9216 uint4)
#define OFF_XH   36864      // 32 chunks x 136 = 4352
#define OFF_XL   41216
#define OFF_HSH  45568      // 8 chunks x 136 = 1088
#define OFF_HSL  46656
#define OFF_EH   47744
#define OFF_EL   48832
#define OFF_T1H  49920
#define OFF_T1L  51008
#define OFF_DEH  52096
#define OFF_DEL  53184
#define OFF_SHI  54272
#define OFF_B1   54336
#define OFF_B2   54400
#define OFF_BG   54464
#define OFF_BMP  54528
#define OFF_RED  54592      // 128
#define SMEM_U32 54720
#define SMEM_BYTES (SMEM_U32 * 4)

__device__ __forceinline__ float fast_sigmoid(float x) {
    return 1.0f / (1.0f + __expf(-x));
}
__device__ __forceinline__ float silu(float x) { return x * fast_sigmoid(x); }

__device__ __forceinline__ void splitpk(float v0, float v1, unsigned &whi, unsigned &wlo) {
    __nv_bfloat16 h0 = __float2bfloat16(v0);
    __nv_bfloat16 h1 = __float2bfloat16(v1);
    float r0 = v0 - __bfloat162float(h0);
    float r1 = v1 - __bfloat162float(h1);
    __nv_bfloat16 l0 = __float2bfloat16(r0);
    __nv_bfloat16 l1 = __float2bfloat16(r1);
    whi = ((unsigned)__bfloat16_as_ushort(h1) << 16) | (unsigned)__bfloat16_as_ushort(h0);
    wlo = ((unsigned)__bfloat16_as_ushort(l1) << 16) | (unsigned)__bfloat16_as_ushort(l0);
}
__device__ __forceinline__ void up2(unsigned w, float &f0, float &f1) {
    f0 = __bfloat162float(__ushort_as_bfloat16((unsigned short)(w & 0xffffu)));
    f1 = __bfloat162float(__ushort_as_bfloat16((unsigned short)(w >> 16)));
}

__device__ __forceinline__ void mma4(float *d, const unsigned *a, unsigned b0, unsigned b1) {
    asm("mma.sync.aligned.m16n8k16.row.col.f32.bf16.bf16.f32 "
        "{%0,%1,%2,%3}, {%4,%5,%6,%7}, {%8,%9}, {%0,%1,%2,%3};"
        : "+f"(d[0]), "+f"(d[1]), "+f"(d[2]), "+f"(d[3])
        : "r"(a[0]), "r"(a[1]), "r"(a[2]), "r"(a[3]), "r"(b0), "r"(b1));
}

__device__ __forceinline__ void barh(int id) {
    asm volatile("barrier.sync %0, 128;" :: "r"(id) : "memory");
}

// GEMM chunk: NKL k16 steps. A-frags from pre-swizzled planes (uint4/lane/chunk),
// B-frags packed {hi,lo} uint4. 3-MMA bf16 split per step.
template <int NKL>
__device__ __forceinline__ void do_gemm(float (&d)[2][4],
    const uint4 *__restrict__ W4,
    const unsigned *__restrict__ Ah, const unsigned *__restrict__ Al,
    int wkkStart, int wr, int wc, int lane)
{
#pragma unroll
    for (int kl = 0; kl < NKL; kl++) {
        const int ci = (kl * 2 + wr) * (CH / 4) + lane;
        uint4 ah4 = ((const uint4 *)Ah)[ci];
        uint4 al4 = ((const uint4 *)Al)[ci];
        const unsigned *ah = (const unsigned *)&ah4;
        const unsigned *al = (const unsigned *)&al4;
        const int kk = wkkStart + kl;
#pragma unroll
        for (int s = 0; s < 2; s++) {
            uint4 b = W4[((kk * 8) + (wc * 2 + s)) * 32 + lane];
            mma4(d[s], ah, b.x, b.y);
            mma4(d[s], ah, b.z, b.w);
            mma4(d[s], al, b.x, b.y);
        }
    }
}

// ---- Precompute weight B-fragments (hi/lo packed uint4) ----
__global__ void prep_kernel(const float *__restrict__ W1, const float *__restrict__ W2,
                            const float *__restrict__ Wg, const float *__restrict__ Wm)
{
    const int kk = blockIdx.x;
    const int t = threadIdx.x;
    const int nt = t >> 5;
    const int lane = t & 31;
    const int g = lane >> 2;
    const int tt = lane & 3;
    const int n = nt * 8 + g;
    const int k0 = tt * 2;

    const float *W;
    int kb;
    if (kk < 16)      { W = W1; kb = kk * 16; }
    else if (kk < 20) { W = W2; kb = (kk - 16) * 16; }
    else if (kk < 28) { W = Wg; kb = (kk - 20) * 16; }
    else if (kk < 32) { W = Wm; kb = (kk - 28) * 16; }
    else              { W = Wm; kb = 128 + (kk - 32) * 16; }

    float w0 = W[(kb + k0) * 64 + n];
    float w1 = W[(kb + k0 + 1) * 64 + n];
    float w2 = W[(kb + k0 + 8) * 64 + n];
    float w3 = W[(kb + k0 + 9) * 64 + n];

    unsigned h0, l0, h1, l1;
    splitpk(w0, w1, h0, l0);
    splitpk(w2, w3, h1, l1);
    g_Wf[(kk * 8 + nt) * 32 + lane] = make_uint4(h0, h1, l0, l1);
}

__global__ void __launch_bounds__(NTH, 1) edge_kernel(
    const float *__restrict__ h, const float *__restrict__ e,
    const float *__restrict__ b1, const float *__restrict__ b2,
    const float *__restrict__ bg, const float *__restrict__ bm,
    const float *__restrict__ Wm,
    float *__restrict__ e_out)
{
    extern __shared__ unsigned smu[];
    const uint4 *W4 = (const uint4 *)(smu + OFF_W);
    unsigned *sXh = smu + OFF_XH, *sXl = smu + OFF_XL;
    unsigned *sHSh = smu + OFF_HSH, *sHSl = smu + OFF_HSL;
    unsigned *sEh = smu + OFF_EH, *sEl = smu + OFF_EL;
    unsigned *sT1h = smu + OFF_T1H, *sT1l = smu + OFF_T1L;
    unsigned *sDEh = smu + OFF_DEH, *sDEl = smu + OFF_DEL;
    float *shi = (float *)(smu + OFF_SHI);
    float *sb1 = (float *)(smu + OFF_B1);
    float *sb2 = (float *)(smu + OFF_B2);
    float *sbg = (float *)(smu + OFF_BG);
    float *sbmp = (float *)(smu + OFF_BMP);
    float *sRed = (float *)(smu + OFF_RED);

    const int tid = threadIdx.x;
    const int blk = blockIdx.x;
    const int b = blk / NN;
    const int i = blk - b * NN;

    const int w = tid >> 5;
    const int lane = tid & 31;
    const int wr = w >> 2;      // half id
    const int wc = w & 3;       // 16-col slab
    const int g = lane >> 2;
    const int t = lane & 3;
    const int bid = 1 + wr;     // named barrier id for this half

    // ---- stage weights into smem ----
    {
        uint4 *dst = (uint4 *)(smu + OFF_W);
        for (int idx = tid; idx < KK_TOTAL * 8 * 32; idx += NTH)
            dst[idx] = g_Wf[idx];
    }
    if (tid < 64) {
        shi[tid] = h[(b * NN + i) * DD + tid];
        sb1[tid] = b1[tid];
        sb2[tid] = b2[tid];
        sbg[tid] = bg[tid];
    }
    __syncthreads();
    if (tid < 64) {   // bm' = bm + ht @ Wm[64:128]
        float acc = bm[tid];
#pragma unroll 8
        for (int k = 0; k < 64; k++)
            acc = fmaf(shi[k], Wm[(64 + k) * 64 + tid], acc);
        sbmp[tid] = acc;
    }

    // stage-A row assignment: rows rbase..rbase+3 within the 32-row tile
    const int rbase = 16 * wr + (w & 3) * 4;
    const int c2 = 2 * lane;
    const float ht0 = shi[c2], ht1 = shi[c2 + 1];
    // per-(row,lane) frag offset for the 64-wide planes (pidx = lane)
    // off(r,pidx) = ((pidx>>3)*2 + (r>>4))*CH + ((r&7)*4 + (pidx&3))*4 + ((pidx>>2)&1)*2 + ((r>>3)&1)
    int offs[4];
#pragma unroll
    for (int p = 0; p < 4; p++) {
        const int r = rbase + p;
        offs[p] = ((lane >> 3) * 2 + (r >> 4)) * CH + ((r & 7) * 4 + (lane & 3)) * 4
                + ((lane >> 2) & 1) * 2 + ((r >> 3) & 1);
    }

    const size_t erow = ((size_t)(b * NN + i)) * NN;
    float2 hs2[4], e2[4];
#pragma unroll
    for (int p = 0; p < 4; p++) {
        const int r = rbase + p;
        hs2[p] = *(const float2 *)&h[(b * NN + r) * DD + c2];
        e2[p]  = *(const float2 *)&e[(erow + r) * DD + c2];
    }
    // write planes for tile 0
#pragma unroll
    for (int p = 0; p < 4; p++) {
        unsigned wh, wl2, eh_, el_;
        splitpk(hs2[p].x, hs2[p].y, wh, wl2);
        sHSh[offs[p]] = wh; sHSl[offs[p]] = wl2;
        splitpk(e2[p].x, e2[p].y, eh_, el_);
        sEh[offs[p]] = eh_; sEl[offs[p]] = el_;
        splitpk(hs2[p].x + ht0, hs2[p].y + ht1, wh, wl2);
        sXh[offs[p]] = wh; sXl[offs[p]] = wl2;
        splitpk(fabsf(hs2[p].x - ht0), fabsf(hs2[p].y - ht1), wh, wl2);
        sXh[offs[p] + 8 * CH] = wh; sXl[offs[p] + 8 * CH] = wl2;
        splitpk(hs2[p].x * ht0, hs2[p].y * ht1, wh, wl2);
        sXh[offs[p] + 16 * CH] = wh; sXl[offs[p] + 16 * CH] = wl2;
        sXh[offs[p] + 24 * CH] = eh_; sXl[offs[p] + 24 * CH] = el_;
    }
    __syncthreads();

    const int ch4 = (wc * 2 + wr) * (CH / 4);     // own epilogue uint4 slot base
    const int cb = 16 * wc + 2 * t;               // col base (add 8*s)
    float aggp[2][2] = {{0.f, 0.f}, {0.f, 0.f}};

    for (int j0 = 0; j0 < NN; j0 += TJ) {
        const bool next = (j0 + TJ) < NN;
        float2 hs2n[4], e2n[4];
        if (next) {
#pragma unroll
            for (int p = 0; p < 4; p++) {
                const int r = j0 + TJ + rbase + p;
                hs2n[p] = *(const float2 *)&h[(b * NN + r) * DD + c2];
                e2n[p]  = *(const float2 *)&e[(erow + r) * DD + c2];
            }
        }

        // ---- GEMM1: t1 = silu(edge_in @ W1 + b1) ----
        {
            float d[2][4] = {{0, 0, 0, 0}, {0, 0, 0, 0}};
            do_gemm<16>(d, W4, sXh, sXl, 0, wr, wc, lane);
            unsigned uh[4], ul[4];
#pragma unroll
            for (int s = 0; s < 2; s++) {
                const float bb0 = sb1[cb + 8 * s], bb1 = sb1[cb + 8 * s + 1];
#pragma unroll
                for (int rh = 0; rh < 2; rh++)
                    splitpk(silu(d[s][2 * rh] + bb0), silu(d[s][2 * rh + 1] + bb1),
                            uh[2 * s + rh], ul[2 * s + rh]);
            }
            ((uint4 *)sT1h)[ch4 + lane] = make_uint4(uh[0], uh[1], uh[2], uh[3]);
            ((uint4 *)sT1l)[ch4 + lane] = make_uint4(ul[0], ul[1], ul[2], ul[3]);
        }
        barh(bid);

        // ---- GEMM2: de = t1 @ W2 + b2 ----
        {
            float d[2][4] = {{0, 0, 0, 0}, {0, 0, 0, 0}};
            do_gemm<4>(d, W4, sT1h, sT1l, 16, wr, wc, lane);
            unsigned uh[4], ul[4];
#pragma unroll
            for (int s = 0; s < 2; s++) {
                const float bb0 = sb2[cb + 8 * s], bb1 = sb2[cb + 8 * s + 1];
#pragma unroll
                for (int rh = 0; rh < 2; rh++)
                    splitpk(d[s][2 * rh] + bb0, d[s][2 * rh + 1] + bb1,
                            uh[2 * s + rh], ul[2 * s + rh]);
            }
            ((uint4 *)sDEh)[ch4 + lane] = make_uint4(uh[0], uh[1], uh[2], uh[3]);
            ((uint4 *)sDEl)[ch4 + lane] = make_uint4(ul[0], ul[1], ul[2], ul[3]);
        }
        barh(bid);

        // ---- GEMM3: eg = sigmoid([e,de]@Wg+bg); e_new = eg*e + (1-eg)*de ----
        float en[2][2][2];
        {
            float d[2][4] = {{0, 0, 0, 0}, {0, 0, 0, 0}};
            do_gemm<4>(d, W4, sEh, sEl, 20, wr, wc, lane);
            do_gemm<4>(d, W4, sDEh, sDEl, 24, wr, wc, lane);
            uint4 E4h = ((const uint4 *)sEh)[ch4 + lane];
            uint4 E4l = ((const uint4 *)sEl)[ch4 + lane];
            uint4 D4h = ((const uint4 *)sDEh)[ch4 + lane];
            uint4 D4l = ((const uint4 *)sDEl)[ch4 + lane];
            const unsigned *pEh = (const unsigned *)&E4h, *pEl = (const unsigned *)&E4l;
            const unsigned *pDh = (const unsigned *)&D4h, *pDl = (const unsigned *)&D4l;
#pragma unroll
            for (int s = 0; s < 2; s++) {
                const float bg0 = sbg[cb + 8 * s], bg1 = sbg[cb + 8 * s + 1];
#pragma unroll
                for (int rh = 0; rh < 2; rh++) {
                    const int comp = 2 * s + rh;
                    float e0, e1, x0, x1, de0, de1, y0, y1;
                    up2(pEh[comp], e0, e1); up2(pEl[comp], x0, x1);
                    up2(pDh[comp], de0, de1); up2(pDl[comp], y0, y1);
                    e0 += x0; e1 += x1; de0 += y0; de1 += y1;
                    const float g0 = fast_sigmoid(d[s][2 * rh] + bg0);
                    const float g1 = fast_sigmoid(d[s][2 * rh + 1] + bg1);
                    en[s][rh][0] = g0 * e0 + (1.0f - g0) * de0;
                    en[s][rh][1] = g1 * e1 + (1.0f - g1) * de1;
                }
            }
        }
        barh(bid);   // all reads of sE/sDE done before overwrite
        {
            unsigned uh[4], ul[4];
#pragma unroll
            for (int s = 0; s < 2; s++)
#pragma unroll
                for (int rh = 0; rh < 2; rh++) {
                    splitpk(en[s][rh][0], en[s][rh][1], uh[2 * s + rh], ul[2 * s + rh]);
                    float2 v; v.x = en[s][rh][0]; v.y = en[s][rh][1];
                    *(float2 *)&e_out[(erow + (j0 + 16 * wr + g + 8 * rh)) * DD + cb + 8 * s] = v;
                }
            ((uint4 *)sEh)[ch4 + lane] = make_uint4(uh[0], uh[1], uh[2], uh[3]);
            ((uint4 *)sEl)[ch4 + lane] = make_uint4(ul[0], ul[1], ul[2], ul[3]);
        }
        barh(bid);

        // ---- GEMM4: msg = silu([hs, ht, e_new]@Wm + bm') ----
        {
            float d[2][4] = {{0, 0, 0, 0}, {0, 0, 0, 0}};
            do_gemm<4>(d, W4, sHSh, sHSl, 28, wr, wc, lane);
            do_gemm<4>(d, W4, sEh, sEl, 32, wr, wc, lane);
            const int jg0 = j0 + 16 * wr + g;
#pragma unroll
            for (int s = 0; s < 2; s++) {
                const float bb0 = sbmp[cb + 8 * s], bb1 = sbmp[cb + 8 * s + 1];
                if (jg0 != i) {
                    aggp[s][0] += silu(d[s][0] + bb0);
                    aggp[s][1] += silu(d[s][1] + bb1);
                }
                if (jg0 + 8 != i) {
                    aggp[s][0] += silu(d[s][2] + bb0);
                    aggp[s][1] += silu(d[s][3] + bb1);
                }
            }
        }
        barh(bid);   // GEMM4 reads done before stage-A overwrite

        if (next) {
#pragma unroll
            for (int p = 0; p < 4; p++) {
                unsigned wh, wl2, eh_, el_;
                splitpk(hs2n[p].x, hs2n[p].y, wh, wl2);
                sHSh[offs[p]] = wh; sHSl[offs[p]] = wl2;
                splitpk(e2n[p].x, e2n[p].y, eh_, el_);
                sEh[offs[p]] = eh_; sEl[offs[p]] = el_;
                splitpk(hs2n[p].x + ht0, hs2n[p].y + ht1, wh, wl2);
                sXh[offs[p]] = wh; sXl[offs[p]] = wl2;
                splitpk(fabsf(hs2n[p].x - ht0), fabsf(hs2n[p].y - ht1), wh, wl2);
                sXh[offs[p] + 8 * CH] = wh; sXl[offs[p] + 8 * CH] = wl2;
                splitpk(hs2n[p].x * ht0, hs2n[p].y * ht1, wh, wl2);
                sXh[offs[p] + 16 * CH] = wh; sXl[offs[p] + 16 * CH] = wl2;
                sXh[offs[p] + 24 * CH] = eh_; sXl[offs[p] + 24 * CH] = el_;
            }
        }
        barh(bid);
    }

    // ---- agg reduction: sum over g lanes, then across halves via smem ----
#pragma unroll
    for (int s = 0; s < 2; s++)
#pragma unroll
        for (int o = 0; o < 2; o++) {
            float v = aggp[s][o];
            v += __shfl_xor_sync(0xffffffffu, v, 4);
            v += __shfl_xor_sync(0xffffffffu, v, 8);
            v += __shfl_xor_sync(0xffffffffu, v, 16);
            aggp[s][o] = v;
        }
    if (lane < 4) {
#pragma unroll
        for (int s = 0; s < 2; s++)
#pragma unroll
            for (int o = 0; o < 2; o++)
                sRed[wr * 64 + 16 * wc + 8 * s + 2 * lane + o] = aggp[s][o];
    }
    __syncthreads();
    if (tid < 64)
        d_agg[(b * NN + i) * DD + tid] = (sRed[tid] + sRed[64 + tid]) * (1.0f / (NN - 1));
}

__global__ void __launch_bounds__(64) node_kernel(
    const float *__restrict__ h,
    const float *__restrict__ Wu, const float *__restrict__ bu,
    const float *__restrict__ Wg, const float *__restrict__ bg,
    float *__restrict__ h_out)
{
    __shared__ float xs[128];
    __shared__ float dhs[64];
    const int node = blockIdx.x;
    const int c = threadIdx.x;

    xs[c] = h[node * 64 + c];
    xs[64 + c] = d_agg[node * 64 + c];
    __syncthreads();

    float acc = bu[c];
#pragma unroll 8
    for (int k = 0; k < 128; k++)
        acc = fmaf(xs[k], Wu[k * 64 + c], acc);
    float dh = acc * fast_sigmoid(acc);
    dhs[c] = dh;
    __syncthreads();

    float a2 = bg[c];
#pragma unroll 8
    for (int k = 0; k < 64; k++)
        a2 = fmaf(xs[k], Wg[k * 64 + c], a2);
#pragma unroll 8
    for (int k = 0; k < 64; k++)
        a2 = fmaf(dhs[k], Wg[(64 + k) * 64 + c], a2);
    float gg = fast_sigmoid(a2);
    h_out[node * 64 + c] = gg * xs[c] + (1.0f - gg) * dh;
}

extern "C" void kernel_launch(void* const* d_in, const int* in_sizes, int n_in,
                              void* d_out, int out_size)
{
    const float* h   = (const float*)d_in[0];
    const float* e   = (const float*)d_in[1];
    const float* W1  = (const float*)d_in[2];
    const float* b1  = (const float*)d_in[3];
    const float* W2  = (const float*)d_in[4];
    const float* b2  = (const float*)d_in[5];
    const float* Weg = (const float*)d_in[6];
    const float* beg = (const float*)d_in[7];
    const float* Wm  = (const float*)d_in[8];
    const float* bm  = (const float*)d_in[9];
    const float* Wu  = (const float*)d_in[10];
    const float* bu  = (const float*)d_in[11];
    const float* Wga = (const float*)d_in[12];
    const float* bga = (const float*)d_in[13];

    float* out = (float*)d_out;
    float* h_out = out;                       // (B,N,D)
    float* e_out = out + BB * NN * DD;        // (B,N,N,D)

    cudaFuncSetAttribute(edge_kernel, cudaFuncAttributeMaxDynamicSharedMemorySize, SMEM_BYTES);

    prep_kernel<<<KK_TOTAL, NTH>>>(W1, W2, Weg, Wm);
    edge_kernel<<<BB * NN, NTH, SMEM_BYTES>>>(h, e, b1, b2, beg, bm, Wm, e_out);
    node_kernel<<<BB * NN, 64>>>(h, Wu, bu, Wga, bga, h_out);
}

// round 6
// speedup vs baseline: 3.4981x; 1.0272x over previous
#include <cuda_runtime.h>
#include <cuda_bf16.h>
#include <math.h>
#include <stdint.h>

#define BB 4
#define NN 384
#define DD 64
#define NTH 256

// k16 steps: G1 (edge_in@W1) kk0-15, G2 (t1@W2) kk16-19,
// G3 ([e,de]@Wg) kk20-27, G4 ([hs,e_new]@Wm') kk28-35 (ht block folded into bias)
#define KK_TOTAL 36
#define NFRAG 8
__device__ uint4 g_Wf[KK_TOTAL * NFRAG * 32];   // {bh0,bh1,bl0,bl1} per (kk,f,lane)
__device__ float d_agg[BB * NN * DD];

// smem: weight frags + biases + shi + reduce
#define SWF_U4   (KK_TOTAL * NFRAG * 32)        // 9216 uint4
#define OFF_B1   (SWF_U4 * 4)                   // u32 offsets
#define OFF_B2   (OFF_B1 + 64)
#define OFF_BG   (OFF_B2 + 64)
#define OFF_BMP  (OFF_BG + 64)
#define OFF_SHI  (OFF_BMP + 64)
#define OFF_RED  (OFF_SHI + 64)                 // 8*64 floats
#define SMEM_U32 (OFF_RED + 512)
#define SMEM_BYTES (SMEM_U32 * 4)

__device__ __forceinline__ float fsig(float x) { return 1.0f / (1.0f + __expf(-x)); }
__device__ __forceinline__ float fsilu(float x) { return x * fsig(x); }

__device__ __forceinline__ void splitpk(float v0, float v1, unsigned &whi, unsigned &wlo) {
    __nv_bfloat16 h0 = __float2bfloat16(v0);
    __nv_bfloat16 h1 = __float2bfloat16(v1);
    __nv_bfloat16 l0 = __float2bfloat16(v0 - __bfloat162float(h0));
    __nv_bfloat16 l1 = __float2bfloat16(v1 - __bfloat162float(h1));
    whi = ((unsigned)__bfloat16_as_ushort(h1) << 16) | (unsigned)__bfloat16_as_ushort(h0);
    wlo = ((unsigned)__bfloat16_as_ushort(l1) << 16) | (unsigned)__bfloat16_as_ushort(l0);
}

__device__ __forceinline__ void mma4(float *d, const unsigned *a, unsigned b0, unsigned b1) {
    asm("mma.sync.aligned.m16n8k16.row.col.f32.bf16.bf16.f32 "
        "{%0,%1,%2,%3}, {%4,%5,%6,%7}, {%8,%9}, {%0,%1,%2,%3};"
        : "+f"(d[0]), "+f"(d[1]), "+f"(d[2]), "+f"(d[3])
        : "r"(a[0]), "r"(a[1]), "r"(a[2]), "r"(a[3]), "r"(b0), "r"(b1));
}

// 3-term bf16-split MMA: Ah*Wh + Al*Wh + Ah*Wl
__device__ __forceinline__ void mma3(float *d, const unsigned *ah, const unsigned *al, uint4 b) {
    mma4(d, ah, b.x, b.y);
    mma4(d, al, b.x, b.y);
    mma4(d, ah, b.z, b.w);
}

// ---- prep: pack weight B-fragments (hi/lo bf16) ----
__global__ void prep_kernel(const float *__restrict__ W1, const float *__restrict__ W2,
                            const float *__restrict__ Wg, const float *__restrict__ Wm)
{
    const int kk = blockIdx.x;          // 0..35
    const int tid = threadIdx.x;        // 256 = 8 f * 32 lanes
    const int f = tid >> 5;
    const int lane = tid & 31;
    const int g = lane >> 2;
    const int t = lane & 3;
    const int n = 8 * f + g;

    const float *W; int kb;
    if (kk < 16)      { W = W1; kb = kk * 16; }
    else if (kk < 20) { W = W2; kb = (kk - 16) * 16; }
    else if (kk < 28) { W = Wg; kb = (kk - 20) * 16; }
    else if (kk < 32) { W = Wm; kb = (kk - 28) * 16; }          // hs rows 0-63
    else              { W = Wm; kb = 128 + (kk - 32) * 16; }    // e_new rows 128-191

    float w0 = W[(kb + 2 * t) * 64 + n];
    float w1 = W[(kb + 2 * t + 1) * 64 + n];
    float w2 = W[(kb + 2 * t + 8) * 64 + n];
    float w3 = W[(kb + 2 * t + 9) * 64 + n];
    unsigned h0, l0, h1, l1;
    splitpk(w0, w1, h0, l0);
    splitpk(w2, w3, h1, l1);
    g_Wf[(kk * NFRAG + f) * 32 + lane] = make_uint4(h0, h1, l0, l1);
}

__global__ void __launch_bounds__(NTH, 1) edge_kernel(
    const float *__restrict__ h, const float *__restrict__ e,
    const float *__restrict__ b1, const float *__restrict__ b2,
    const float *__restrict__ bg, const float *__restrict__ bm,
    const float *__restrict__ Wm,
    float *__restrict__ e_out)
{
    extern __shared__ unsigned smu[];
    const uint4 *sWf = (const uint4 *)smu;
    float *sb1 = (float *)(smu + OFF_B1);
    float *sb2 = (float *)(smu + OFF_B2);
    float *sbg = (float *)(smu + OFF_BG);
    float *sbmp = (float *)(smu + OFF_BMP);
    float *shi = (float *)(smu + OFF_SHI);
    float *sred = (float *)(smu + OFF_RED);

    const int tid = threadIdx.x;
    const int w = tid >> 5;
    const int lane = tid & 31;
    const int g = lane >> 2;
    const int t = lane & 3;

    const int blk = blockIdx.x;
    const int b = blk / NN;
    const int i = blk - b * NN;
    const size_t erow = ((size_t)(b * NN + i)) * NN;

    // ---- stage weights + biases + h_i ----
    {
        uint4 *dst = (uint4 *)smu;
        for (int idx = tid; idx < SWF_U4; idx += NTH) dst[idx] = g_Wf[idx];
    }
    if (tid < 64) {
        sb1[tid] = b1[tid];
        sb2[tid] = b2[tid];
        sbg[tid] = bg[tid];
        shi[tid] = h[(b * NN + i) * DD + tid];
    }
    __syncthreads();
    if (tid < 64) {   // bm' = bm + ht @ Wm[64:128]
        float a = bm[tid];
#pragma unroll 8
        for (int k = 0; k < 64; k++) a = fmaf(shi[k], Wm[(64 + k) * 64 + tid], a);
        sbmp[tid] = a;
    }
    __syncthreads();

    // per-thread ht values at owned cols (16m + 8p + 2t)
    float2 htv[4][2];
#pragma unroll
    for (int m = 0; m < 4; m++)
#pragma unroll
        for (int p = 0; p < 2; p++)
            htv[m][p] = *(const float2 *)&shi[16 * m + 8 * p + 2 * t];

    float2 aggc[8];
#pragma unroll
    for (int f = 0; f < 8; f++) aggc[f] = make_float2(0.f, 0.f);

    for (int j0 = 0; j0 < NN; j0 += 128) {
        const int rA = j0 + 16 * w + g;
        const int rB = rA + 8;

        // ---- load hs, e rows (cols 16m+8p+2t, float2) ----
        float2 hsA[4][2], hsB[4][2], eA[4][2], eB[4][2];
        const float *hA = &h[(b * NN + rA) * DD];
        const float *hB = &h[(b * NN + rB) * DD];
        const float *epA = &e[(erow + rA) * DD];
        const float *epB = &e[(erow + rB) * DD];
#pragma unroll
        for (int m = 0; m < 4; m++)
#pragma unroll
            for (int p = 0; p < 2; p++) {
                const int c = 16 * m + 8 * p + 2 * t;
                hsA[m][p] = *(const float2 *)&hA[c];
                hsB[m][p] = *(const float2 *)&hB[c];
                eA[m][p]  = *(const float2 *)&epA[c];
                eB[m][p]  = *(const float2 *)&epB[c];
            }

        // ---- G1: D = edge_in @ W1 ----
        float D[8][4];
#pragma unroll
        for (int f = 0; f < 8; f++) { D[f][0] = D[f][1] = D[f][2] = D[f][3] = 0.f; }
#pragma unroll
        for (int kk = 0; kk < 16; kk++) {
            const int m = kk & 3, F = kk >> 2;
            unsigned ah[4], al[4];
#pragma unroll
            for (int p = 0; p < 2; p++) {
                float2 a0, b0;
                if (F == 0) {
                    a0 = make_float2(hsA[m][p].x + htv[m][p].x, hsA[m][p].y + htv[m][p].y);
                    b0 = make_float2(hsB[m][p].x + htv[m][p].x, hsB[m][p].y + htv[m][p].y);
                } else if (F == 1) {
                    a0 = make_float2(fabsf(hsA[m][p].x - htv[m][p].x), fabsf(hsA[m][p].y - htv[m][p].y));
                    b0 = make_float2(fabsf(hsB[m][p].x - htv[m][p].x), fabsf(hsB[m][p].y - htv[m][p].y));
                } else if (F == 2) {
                    a0 = make_float2(hsA[m][p].x * htv[m][p].x, hsA[m][p].y * htv[m][p].y);
                    b0 = make_float2(hsB[m][p].x * htv[m][p].x, hsB[m][p].y * htv[m][p].y);
                } else {
                    a0 = eA[m][p];
                    b0 = eB[m][p];
                }
                splitpk(a0.x, a0.y, ah[2 * p], al[2 * p]);
                splitpk(b0.x, b0.y, ah[2 * p + 1], al[2 * p + 1]);
            }
#pragma unroll
            for (int f = 0; f < 8; f++)
                mma3(D[f], ah, al, sWf[(kk * NFRAG + f) * 32 + lane]);
        }

        // ---- t1 = silu(D + b1) as A-frags ----
        unsigned t1h[4][4], t1l[4][4];
#pragma unroll
        for (int m = 0; m < 4; m++) {
            const int f0 = 2 * m, f1 = 2 * m + 1;
            float2 bb0 = *(const float2 *)&sb1[8 * f0 + 2 * t];
            float2 bb1 = *(const float2 *)&sb1[8 * f1 + 2 * t];
            splitpk(fsilu(D[f0][0] + bb0.x), fsilu(D[f0][1] + bb0.y), t1h[m][0], t1l[m][0]);
            splitpk(fsilu(D[f0][2] + bb0.x), fsilu(D[f0][3] + bb0.y), t1h[m][1], t1l[m][1]);
            splitpk(fsilu(D[f1][0] + bb1.x), fsilu(D[f1][1] + bb1.y), t1h[m][2], t1l[m][2]);
            splitpk(fsilu(D[f1][2] + bb1.x), fsilu(D[f1][3] + bb1.y), t1h[m][3], t1l[m][3]);
        }

        // ---- G2: D2 = t1 @ W2 (+b2 in place) ----
        float D2[8][4];
#pragma unroll
        for (int f = 0; f < 8; f++) { D2[f][0] = D2[f][1] = D2[f][2] = D2[f][3] = 0.f; }
#pragma unroll
        for (int kk = 0; kk < 4; kk++)
#pragma unroll
            for (int f = 0; f < 8; f++)
                mma3(D2[f], t1h[kk], t1l[kk], sWf[((16 + kk) * NFRAG + f) * 32 + lane]);
#pragma unroll
        for (int f = 0; f < 8; f++) {
            float2 bb = *(const float2 *)&sb2[8 * f + 2 * t];
            D2[f][0] += bb.x; D2[f][1] += bb.y; D2[f][2] += bb.x; D2[f][3] += bb.y;
        }

        // ---- G3: D3 = [e, de] @ Wg ----
        float D3[8][4];
#pragma unroll
        for (int f = 0; f < 8; f++) { D3[f][0] = D3[f][1] = D3[f][2] = D3[f][3] = 0.f; }
#pragma unroll
        for (int kk = 0; kk < 4; kk++) {     // e block
            unsigned ah[4], al[4];
            splitpk(eA[kk][0].x, eA[kk][0].y, ah[0], al[0]);
            splitpk(eB[kk][0].x, eB[kk][0].y, ah[1], al[1]);
            splitpk(eA[kk][1].x, eA[kk][1].y, ah[2], al[2]);
            splitpk(eB[kk][1].x, eB[kk][1].y, ah[3], al[3]);
#pragma unroll
            for (int f = 0; f < 8; f++)
                mma3(D3[f], ah, al, sWf[((20 + kk) * NFRAG + f) * 32 + lane]);
        }
#pragma unroll
        for (int kk = 0; kk < 4; kk++) {     // de block (from D2 regs)
            unsigned ah[4], al[4];
            splitpk(D2[2 * kk][0], D2[2 * kk][1], ah[0], al[0]);
            splitpk(D2[2 * kk][2], D2[2 * kk][3], ah[1], al[1]);
            splitpk(D2[2 * kk + 1][0], D2[2 * kk + 1][1], ah[2], al[2]);
            splitpk(D2[2 * kk + 1][2], D2[2 * kk + 1][3], ah[3], al[3]);
#pragma unroll
            for (int f = 0; f < 8; f++)
                mma3(D3[f], ah, al, sWf[((24 + kk) * NFRAG + f) * 32 + lane]);
        }

        // ---- e_new = sig(D3+bg)*e + (1-sig)*de; store + keep in eA/eB ----
        float *eoA = &e_out[(erow + rA) * DD];
        float *eoB = &e_out[(erow + rB) * DD];
#pragma unroll
        for (int m = 0; m < 4; m++)
#pragma unroll
            for (int p = 0; p < 2; p++) {
                const int f = 2 * m + p;
                float2 bb = *(const float2 *)&sbg[8 * f + 2 * t];
                float g0 = fsig(D3[f][0] + bb.x), g1 = fsig(D3[f][1] + bb.y);
                float g2 = fsig(D3[f][2] + bb.x), g3 = fsig(D3[f][3] + bb.y);
                float2 nA, nB;
                nA.x = g0 * eA[m][p].x + (1.f - g0) * D2[f][0];
                nA.y = g1 * eA[m][p].y + (1.f - g1) * D2[f][1];
                nB.x = g2 * eB[m][p].x + (1.f - g2) * D2[f][2];
                nB.y = g3 * eB[m][p].y + (1.f - g3) * D2[f][3];
                eA[m][p] = nA; eB[m][p] = nB;
                const int c = 16 * m + 8 * p + 2 * t;
                *(float2 *)&eoA[c] = nA;
                *(float2 *)&eoB[c] = nB;
            }

        // ---- G4: D4 = [hs, e_new] @ Wm' ----
        float D4[8][4];
#pragma unroll
        for (int f = 0; f < 8; f++) { D4[f][0] = D4[f][1] = D4[f][2] = D4[f][3] = 0.f; }
#pragma unroll
        for (int kk = 0; kk < 4; kk++) {     // hs block
            unsigned ah[4], al[4];
            splitpk(hsA[kk][0].x, hsA[kk][0].y, ah[0], al[0]);
            splitpk(hsB[kk][0].x, hsB[kk][0].y, ah[1], al[1]);
            splitpk(hsA[kk][1].x, hsA[kk][1].y, ah[2], al[2]);
            splitpk(hsB[kk][1].x, hsB[kk][1].y, ah[3], al[3]);
#pragma unroll
            for (int f = 0; f < 8; f++)
                mma3(D4[f], ah, al, sWf[((28 + kk) * NFRAG + f) * 32 + lane]);
        }
#pragma unroll
        for (int kk = 0; kk < 4; kk++) {     // e_new block
            unsigned ah[4], al[4];
            splitpk(eA[kk][0].x, eA[kk][0].y, ah[0], al[0]);
            splitpk(eB[kk][0].x, eB[kk][0].y, ah[1], al[1]);
            splitpk(eA[kk][1].x, eA[kk][1].y, ah[2], al[2]);
            splitpk(eB[kk][1].x, eB[kk][1].y, ah[3], al[3]);
#pragma unroll
            for (int f = 0; f < 8; f++)
                mma3(D4[f], ah, al, sWf[((32 + kk) * NFRAG + f) * 32 + lane]);
        }

        // ---- msg = silu(D4 + bm'), diagonal mask, column-accumulate ----
        const bool mA = (rA != i), mB = (rB != i);
#pragma unroll
        for (int f = 0; f < 8; f++) {
            float2 bb = *(const float2 *)&sbmp[8 * f + 2 * t];
            float m0 = fsilu(D4[f][0] + bb.x), m1 = fsilu(D4[f][1] + bb.y);
            float m2 = fsilu(D4[f][2] + bb.x), m3 = fsilu(D4[f][3] + bb.y);
            aggc[f].x += (mA ? m0 : 0.f) + (mB ? m2 : 0.f);
            aggc[f].y += (mA ? m1 : 0.f) + (mB ? m3 : 0.f);
        }
    }

    // ---- agg reduce: over g lanes (shfl), then over warps (smem) ----
#pragma unroll
    for (int f = 0; f < 8; f++) {
        float x = aggc[f].x, y = aggc[f].y;
        x += __shfl_xor_sync(0xffffffffu, x, 4);
        x += __shfl_xor_sync(0xffffffffu, x, 8);
        x += __shfl_xor_sync(0xffffffffu, x, 16);
        y += __shfl_xor_sync(0xffffffffu, y, 4);
        y += __shfl_xor_sync(0xffffffffu, y, 8);
        y += __shfl_xor_sync(0xffffffffu, y, 16);
        aggc[f].x = x; aggc[f].y = y;
    }
    if (lane < 4) {
#pragma unroll
        for (int f = 0; f < 8; f++) {
            sred[w * 64 + 8 * f + 2 * lane] = aggc[f].x;
            sred[w * 64 + 8 * f + 2 * lane + 1] = aggc[f].y;
        }
    }
    __syncthreads();
    if (tid < 64) {
        float s = 0.f;
#pragma unroll
        for (int ww = 0; ww < 8; ww++) s += sred[ww * 64 + tid];
        d_agg[(b * NN + i) * DD + tid] = s * (1.0f / (NN - 1));
    }
}

__global__ void __launch_bounds__(64) node_kernel(
    const float *__restrict__ h,
    const float *__restrict__ Wu, const float *__restrict__ bu,
    const float *__restrict__ Wg, const float *__restrict__ bg,
    float *__restrict__ h_out)
{
    __shared__ float xs[128];
    __shared__ float dhs[64];
    const int node = blockIdx.x;
    const int c = threadIdx.x;

    xs[c] = h[node * 64 + c];
    xs[64 + c] = d_agg[node * 64 + c];
    __syncthreads();

    float acc = bu[c];
#pragma unroll 8
    for (int k = 0; k < 128; k++) acc = fmaf(xs[k], Wu[k * 64 + c], acc);
    float dh = acc * fsig(acc);
    dhs[c] = dh;
    __syncthreads();

    float a2 = bg[c];
#pragma unroll 8
    for (int k = 0; k < 64; k++) a2 = fmaf(xs[k], Wg[k * 64 + c], a2);
#pragma unroll 8
    for (int k = 0; k < 64; k++) a2 = fmaf(dhs[k], Wg[(64 + k) * 64 + c], a2);
    float gg = fsig(a2);
    h_out[node * 64 + c] = gg * xs[c] + (1.0f - gg) * dh;
}

extern "C" void kernel_launch(void* const* d_in, const int* in_sizes, int n_in,
                              void* d_out, int out_size)
{
    const float* h   = (const float*)d_in[0];
    const float* e   = (const float*)d_in[1];
    const float* W1  = (const float*)d_in[2];
    const float* b1  = (const float*)d_in[3];
    const float* W2  = (const float*)d_in[4];
    const float* b2  = (const float*)d_in[5];
    const float* Weg = (const float*)d_in[6];
    const float* beg = (const float*)d_in[7];
    const float* Wm  = (const float*)d_in[8];
    const float* bm  = (const float*)d_in[9];
    const float* Wu  = (const float*)d_in[10];
    const float* bu  = (const float*)d_in[11];
    const float* Wga = (const float*)d_in[12];
    const float* bga = (const float*)d_in[13];

    float* out = (float*)d_out;
    float* h_out = out;                       // (B,N,D)
    float* e_out = out + BB * NN * DD;        // (B,N,N,D)

    cudaFuncSetAttribute(edge_kernel, cudaFuncAttributeMaxDynamicSharedMemorySize, SMEM_BYTES);

    prep_kernel<<<KK_TOTAL, NTH>>>(W1, W2, Weg, Wm);
    edge_kernel<<<BB * NN, NTH, SMEM_BYTES>>>(h, e, b1, b2, beg, bm, Wm, e_out);
    node_kernel<<<BB * NN, 64>>>(h, Wu, bu, Wga, bga, h_out);
}